// round 15
// baseline (speedup 1.0000x reference)
#include <cuda_runtime.h>
#include <cuda_fp16.h>
#include <cstdint>

// ---------------------------------------------------------------------------
// SO3Linear (L=3, B=1024, C=256) via pure-fp16 mma.sync GEMM (1 term),
// with producer/consumer overlap in a single kernel.
//
//  K1 wsplit+setup : W fp32 -> Wt[w][co][ci] fp16; block(0,0,0) builds
//                    range tables from seg1/seg2.
//  K2 xhalf        : x fp32 -> fp16
//  (memset)        : zero per-(btile,M) ready flags
//  K3 so3_main     : 768 CTAs, 128 threads.
//     bids 0..255   BUILD role: (btile, M): A[g in M][64 b][ci] fp16 from x;
//                   release flag[btile][M] (threadfence + atomicExch).
//     bids 256..767 MMA role: (btile, co, M): acquire flag, then R10-best
//                   GEMM: 4 warps (2m x 2n, warp 32x64), KT=64, 2-stage
//                   cp.async (.cg reads L2 -> sees build stores after acquire).
//  err: x,A,W fp16 rounding => ~3.6e-4 << 1e-3 (measured R12-R14).
// ---------------------------------------------------------------------------

#define NORD     16
#define CI       256
#define CO       256
#define G_MAX    156
#define NW_MAX   40
#define B_MAX    1024
#define NZ_M_MAX 48     // max nonzeros per output order (actual max 39)

// ---- device scratch ----
__device__ __half g_xh[(size_t)B_MAX * NORD * CI];    // x fp16
__device__ __half g_af[(size_t)G_MAX * B_MAX * CI];   // A fp16
__device__ __half g_wf[(size_t)NW_MAX * CO * CI];     // W fp16 (transposed)
__device__ int g_gs[G_MAX + 1];
__device__ int g_mg[NORD + 1];
__device__ int g_flag[256];                           // [btile][M] ready flags

// heavy-orders-first schedule (groups/M: l=2 ->11, l=3 ->10, l=1 ->9, l=0 ->4)
__constant__ int c_morder[NORD] = {4,5,6,7,8, 9,10,11,12,13,14,15, 1,2,3, 0};

#define SWZ(o) ((o) ^ (((o) >> 3) & 0x70))

__device__ __forceinline__ uint32_t smem_u32(const void* p) {
    uint32_t a;
    asm("{ .reg .u64 t; cvta.to.shared.u64 t, %1; cvt.u32.u64 %0, t; }" : "=r"(a) : "l"(p));
    return a;
}
__device__ __forceinline__ void cp16(uint32_t dst, const void* src) {
    asm volatile("cp.async.cg.shared.global [%0], [%1], 16;" :: "r"(dst), "l"(src) : "memory");
}
#define CP_COMMIT()  asm volatile("cp.async.commit_group;" ::: "memory")
#define CP_WAIT(N)   asm volatile("cp.async.wait_group %0;" :: "n"(N) : "memory")

__device__ __forceinline__ void ldsm4(uint32_t r[4], uint32_t addr) {
    asm volatile("ldmatrix.sync.aligned.m8n8.x4.shared.b16 {%0,%1,%2,%3}, [%4];"
                 : "=r"(r[0]), "=r"(r[1]), "=r"(r[2]), "=r"(r[3]) : "r"(addr));
}
__device__ __forceinline__ void mma16816(float c[4], const uint32_t a[4],
                                         uint32_t b0, uint32_t b1) {
    asm volatile(
        "mma.sync.aligned.m16n8k16.row.col.f32.f16.f16.f32 "
        "{%0,%1,%2,%3}, {%4,%5,%6,%7}, {%8,%9}, {%0,%1,%2,%3};"
        : "+f"(c[0]), "+f"(c[1]), "+f"(c[2]), "+f"(c[3])
        : "r"(a[0]), "r"(a[1]), "r"(a[2]), "r"(a[3]), "r"(b0), "r"(b1));
}

// ---------------------------------------------------------------------------
// K1: transpose weights to fp16 + (block 0) build range tables.
// ---------------------------------------------------------------------------
__global__ __launch_bounds__(256) void wsplit(const float* __restrict__ weight,
                                              const int* __restrict__ seg1,
                                              const int* __restrict__ seg2,
                                              int nnz, int G) {
    __shared__ float tile[32][33];
    const int w  = blockIdx.z;
    const int bx = blockIdx.x;   // co block
    const int by = blockIdx.y;   // ci block
    const int tx = threadIdx.x & 31;
    const int ty = threadIdx.x >> 5;

    if (bx == 0 && by == 0 && w == 0) {
        int tid = threadIdx.x;
        for (int i = tid; i < nnz; i += blockDim.x) {
            if (i == 0) g_gs[seg1[0]] = 0;
            else if (seg1[i] != seg1[i - 1]) g_gs[seg1[i]] = i;
        }
        for (int i = tid; i < G; i += blockDim.x) {
            if (i == 0) g_mg[seg2[0]] = 0;
            else if (seg2[i] != seg2[i - 1]) g_mg[seg2[i]] = i;
        }
        if (tid == 0) { g_gs[G] = nnz; g_mg[NORD] = G; }
    }

    const float* in = weight + (size_t)w * CI * CO;
#pragma unroll
    for (int j = 0; j < 4; ++j) {
        int r = ty + 8 * j;
        tile[r][tx] = in[(size_t)(by * 32 + r) * CO + bx * 32 + tx];
    }
    __syncthreads();
#pragma unroll
    for (int j = 0; j < 4; ++j) {
        int r = ty + 8 * j;
        float v = tile[tx][r];
        size_t o = ((size_t)w * CO + (bx * 32 + r)) * CI + by * 32 + tx;
        g_wf[o] = __float2half(v);
    }
}

// ---------------------------------------------------------------------------
// K2: x -> fp16
// ---------------------------------------------------------------------------
__global__ __launch_bounds__(256) void xhalf(const float* __restrict__ x, int n4) {
    int i = blockIdx.x * 256 + threadIdx.x;
    if (i < n4) {
        float4 v = __ldg(reinterpret_cast<const float4*>(x) + i);
        __half2 a = __floats2half2_rn(v.x, v.y);
        __half2 b = __floats2half2_rn(v.z, v.w);
        reinterpret_cast<uint2*>(g_xh)[i] =
            make_uint2(*(uint32_t*)&a, *(uint32_t*)&b);
    }
}

// ---------------------------------------------------------------------------
// K3: combined build + MMA kernel. 768 CTAs x 128 threads, 50KB dyn smem,
// 4 CTAs/SM. Build CTAs occupy the lowest 256 bids -> wave-1 residency.
// ---------------------------------------------------------------------------
#define KT          64
#define OFF_W       8192
#define STAGE_BYTES 24576
#define SMEM_DYN    (2 * STAGE_BYTES + 1024)

__device__ __forceinline__ void load_stage(uint32_t st,
                                           const char* gA, const char* gW,
                                           int tid) {
#pragma unroll
    for (int i = 0; i < 4; ++i) {          // A: 64 rows x 8 chunks of 16B
        int idx = tid + i * 128;
        int r = idx >> 3, c = idx & 7;
        cp16(st + SWZ(r * 128 + c * 16), gA + (size_t)r * (CI * 2) + c * 16);
    }
#pragma unroll
    for (int i = 0; i < 8; ++i) {          // W: 128 rows x 8 chunks
        int idx = tid + i * 128;
        int r = idx >> 3, c = idx & 7;
        cp16(st + OFF_W + SWZ(r * 128 + c * 16), gW + (size_t)r * (CI * 2) + c * 16);
    }
}

__global__ __launch_bounds__(128, 4) void so3_main(
    const int* __restrict__ l_ind,
    const float* __restrict__ sh,
    const float* __restrict__ CG,
    const int* __restrict__ M1,
    const int* __restrict__ M2,
    float* __restrict__ out,
    int Bn) {

    extern __shared__ char smem[];
    const uint32_t sb   = smem_u32(smem);
    const uint32_t base = (sb + 1023) & ~1023u;
    char* dynp = smem + (base - sb);

    const int bid = blockIdx.x;
    const int tid = threadIdx.x;

    if (bid < 256) {
        // ================= BUILD role: (btile, M) =================
        const int bt = bid >> 4;
        const int M  = c_morder[bid & 15];
        const int gbeg = g_mg[M];
        const int gend = g_mg[M + 1];
        const int ng   = gend - gbeg;
        const int nzbeg = g_gs[gbeg];
        const int nloc  = g_gs[gend] - nzbeg;

        float* coef = reinterpret_cast<float*>(dynp);                 // [48][64]
        int*   m1s  = reinterpret_cast<int*>(dynp + 48 * 64 * 4);     // [48]
        int*   go   = reinterpret_cast<int*>(dynp + 48 * 64 * 4 + 192); // [12]

        for (int i = tid; i <= ng; i += 128) go[i] = g_gs[gbeg + i] - nzbeg;
        for (int i = tid; i < nloc; i += 128) m1s[i] = M1[nzbeg + i] * CI;
        for (int idx = tid; idx < nloc * 64; idx += 128) {
            int i = idx >> 6, lb = idx & 63;
            coef[i * 64 + lb] =
                CG[nzbeg + i] * sh[(size_t)(bt * 64 + lb) * NORD + M2[nzbeg + i]];
        }
        __syncthreads();

        const int bsub = tid >> 5;           // 0..3
        const int c8   = (tid & 31) * 8;     // 8 ci per thread

        for (int bb = 0; bb < 16; ++bb) {
            const int lb = bb * 4 + bsub;
            const int b  = bt * 64 + lb;
            const __half* xb = g_xh + (size_t)b * NORD * CI + c8;

            for (int gi = 0; gi < ng; ++gi) {
                float acc[8];
#pragma unroll
                for (int j = 0; j < 8; ++j) acc[j] = 0.f;
                const int e = go[gi + 1];
                for (int i = go[gi]; i < e; ++i) {
                    const float c = coef[i * 64 + lb];
                    uint4 v = *reinterpret_cast<const uint4*>(xb + m1s[i]);
                    float2 f0 = __half22float2(*reinterpret_cast<__half2*>(&v.x));
                    float2 f1 = __half22float2(*reinterpret_cast<__half2*>(&v.y));
                    float2 f2 = __half22float2(*reinterpret_cast<__half2*>(&v.z));
                    float2 f3 = __half22float2(*reinterpret_cast<__half2*>(&v.w));
                    acc[0] = fmaf(c, f0.x, acc[0]);
                    acc[1] = fmaf(c, f0.y, acc[1]);
                    acc[2] = fmaf(c, f1.x, acc[2]);
                    acc[3] = fmaf(c, f1.y, acc[3]);
                    acc[4] = fmaf(c, f2.x, acc[4]);
                    acc[5] = fmaf(c, f2.y, acc[5]);
                    acc[6] = fmaf(c, f3.x, acc[6]);
                    acc[7] = fmaf(c, f3.y, acc[7]);
                }
                __half2 p0 = __floats2half2_rn(acc[0], acc[1]);
                __half2 p1 = __floats2half2_rn(acc[2], acc[3]);
                __half2 p2 = __floats2half2_rn(acc[4], acc[5]);
                __half2 p3 = __floats2half2_rn(acc[6], acc[7]);
                uint4 v = make_uint4(*(uint32_t*)&p0, *(uint32_t*)&p1,
                                     *(uint32_t*)&p2, *(uint32_t*)&p3);
                *reinterpret_cast<uint4*>(
                    g_af + ((size_t)(gbeg + gi) * Bn + b) * CI + c8) = v;
            }
        }

        __syncthreads();
        __threadfence();
        if (tid == 0) atomicExch(&g_flag[bt * 16 + M], 1);
        return;
    }

    // ================= MMA role: (btile, co, M) =================
    const int r    = bid - 256;
    const int bt   = r & 15;
    const int cozi = (r >> 4) & 1;
    const int M    = c_morder[r >> 5];

    // acquire: wait until this (btile, M) slab of g_af is published
    if (tid == 0) {
        while (atomicAdd(&g_flag[bt * 16 + M], 0) == 0) __nanosleep(128);
    }
    __syncthreads();

    const int wid  = tid >> 5;
    const int lane = tid & 31;
    const int wm   = wid & 1;          // 2 m-warps (32 rows each)
    const int wn   = wid >> 1;         // 2 n-warps (64 cols each)

    const int b0  = bt * 64;
    const int cob = cozi * 128;
    const int gbeg = g_mg[M];
    const int gend = g_mg[M + 1];
    const int T = (gend - gbeg) * (CI / KT);   // k-tiles (4 per group)

    float acc[2][8][4];
#pragma unroll
    for (int i = 0; i < 2; ++i)
#pragma unroll
        for (int j = 0; j < 8; ++j)
#pragma unroll
            for (int q = 0; q < 4; ++q) acc[i][j][q] = 0.f;

    auto srcA = [&](int t) -> const char* {
        int g = gbeg + (t >> 2), kc = t & 3;
        return (const char*)g_af + (((size_t)g * Bn + b0) * CI + kc * KT) * 2;
    };
    auto srcW = [&](int t) -> const char* {
        int g = gbeg + (t >> 2), kc = t & 3;
        int w = __ldg(l_ind + g);
        return (const char*)g_wf + (((size_t)w * CO + cob) * CI + kc * KT) * 2;
    };

    load_stage(base, srcA(0), srcW(0), tid);
    CP_COMMIT();

    const int arow = wm * 32 + (lane & 15);
    const int acol = (lane >> 4) * 16;
    const int wrow = wn * 64 + (lane & 7) + ((lane >> 4) << 3);
    const int wcol = ((lane >> 3) & 1) * 16;

    for (int t = 0; t < T; ++t) {
        const uint32_t st = base + (uint32_t)(t & 1) * STAGE_BYTES;

        if (t + 1 < T) {
            const uint32_t stn = base + (uint32_t)((t + 1) & 1) * STAGE_BYTES;
            load_stage(stn, srcA(t + 1), srcW(t + 1), tid);
            CP_COMMIT();
            CP_WAIT(1);
        } else {
            CP_WAIT(0);
        }
        __syncthreads();

#pragma unroll
        for (int ks = 0; ks < KT / 16; ++ks) {
            const int kb = ks * 32;
            uint32_t af[2][4];
#pragma unroll
            for (int mi = 0; mi < 2; ++mi) {
                uint32_t ad = st + SWZ((arow + mi * 16) * 128 + kb + acol);
                ldsm4(af[mi], ad);
            }
#pragma unroll
            for (int j = 0; j < 4; ++j) {
                uint32_t wf[4];
                uint32_t wd = st + OFF_W + SWZ((wrow + j * 16) * 128 + kb + wcol);
                ldsm4(wf, wd);
#pragma unroll
                for (int mi = 0; mi < 2; ++mi)
#pragma unroll
                    for (int s = 0; s < 2; ++s)
                        mma16816(acc[mi][j * 2 + s], af[mi], wf[s * 2], wf[s * 2 + 1]);
            }
        }
        __syncthreads();
    }

#pragma unroll
    for (int mi = 0; mi < 2; ++mi) {
        const int m0 = b0 + wm * 32 + mi * 16 + (lane >> 2);
#pragma unroll
        for (int j = 0; j < 8; ++j) {
            const int n = cob + wn * 64 + j * 8 + (lane & 3) * 2;
            float* p0 = out + ((size_t)m0 * NORD + M) * CO + n;
            float* p1 = out + ((size_t)(m0 + 8) * NORD + M) * CO + n;
            *(float2*)p0 = make_float2(acc[mi][j][0], acc[mi][j][1]);
            *(float2*)p1 = make_float2(acc[mi][j][2], acc[mi][j][3]);
        }
    }
}

// ---------------------------------------------------------------------------
// Inputs: x, sh, weight, CG_vals, M1, M2, seg1, l_ind, seg2, num_orders_out
// ---------------------------------------------------------------------------
extern "C" void kernel_launch(void* const* d_in, const int* in_sizes, int n_in,
                              void* d_out, int out_size) {
    const float* x      = (const float*)d_in[0];
    const float* sh     = (const float*)d_in[1];
    const float* weight = (const float*)d_in[2];
    const float* CG     = (const float*)d_in[3];
    const int*   M1     = (const int*)d_in[4];
    const int*   M2     = (const int*)d_in[5];
    const int*   seg1   = (const int*)d_in[6];
    const int*   l_ind  = (const int*)d_in[7];
    const int*   seg2   = (const int*)d_in[8];
    float*       out    = (float*)d_out;

    const int nnz = in_sizes[4];
    const int G   = in_sizes[7];
    const int Bn  = in_sizes[1] / NORD;
    const int n_w = in_sizes[2] / (CI * CO);
    const int xn4 = in_sizes[0] / 4;

    static void* flag_addr = nullptr;
    static bool attr_set = false;
    if (!attr_set) {
        cudaFuncSetAttribute(so3_main, cudaFuncAttributeMaxDynamicSharedMemorySize, SMEM_DYN);
        cudaGetSymbolAddress(&flag_addr, g_flag);
        attr_set = true;
    }

    cudaMemsetAsync(flag_addr, 0, 256 * sizeof(int));
    {
        dim3 grid(CO / 32, CI / 32, n_w);
        wsplit<<<grid, 256>>>(weight, seg1, seg2, nnz, G);
    }
    xhalf<<<(xn4 + 255) / 256, 256>>>(x, xn4);

    so3_main<<<768, 128, SMEM_DYN>>>(l_ind, sh, CG, M1, M2, out, Bn);
}

// round 16
// speedup vs baseline: 1.4427x; 1.4427x over previous
#include <cuda_runtime.h>
#include <cuda_fp16.h>
#include <cstdint>

// ---------------------------------------------------------------------------
// SO3Linear (L=3, B=1024, C=256) via pure-fp16 mma.sync GEMM (1 term).
//
//  K1 prep        : blocks 0..2175  -> W fp32 -> Wt[w][co][ci] fp16
//                   (block 0 also builds range tables from seg1/seg2);
//                   blocks 2176..   -> x fp32 -> fp16.
//  K2 build_inter : inter[g][b][ci] -> A[g][b][ci] fp16; reads fp16 x.
//                   NORMAL stores (g_af L2 residency is load-bearing: R13's
//                   __stcs cost +35us on so3_mma).
//  K3 so3_mma     : per CTA (64 b, 128 co, order M): fp32 accum of sum_g
//                   A@W. 4 warps (2m x 2n, warp tile 32x64), KT=64,
//                   2-stage cp.async, 4 CTAs/SM, heavy-M-first. (R10/R14 best.)
//  err: x,A,W fp16 rounding => ~3.6e-4 << 1e-3 (measured R12-R15).
// ---------------------------------------------------------------------------

#define NORD     16
#define CI       256
#define CO       256
#define G_MAX    156
#define NNZ_MAX  512
#define NW_MAX   40
#define B_MAX    1024

// ---- device scratch ----
__device__ __half g_xh[(size_t)B_MAX * NORD * CI];    // x fp16
__device__ __half g_af[(size_t)G_MAX * B_MAX * CI];   // A fp16
__device__ __half g_wf[(size_t)NW_MAX * CO * CI];     // W fp16 (transposed)
__device__ int g_gs[G_MAX + 1];
__device__ int g_mg[NORD + 1];

// heavy-orders-first schedule (groups/M: l=2 ->11, l=3 ->10, l=1 ->9, l=0 ->4)
__constant__ int c_morder[NORD] = {4,5,6,7,8, 9,10,11,12,13,14,15, 1,2,3, 0};

#define SWZ(o) ((o) ^ (((o) >> 3) & 0x70))

__device__ __forceinline__ uint32_t smem_u32(const void* p) {
    uint32_t a;
    asm("{ .reg .u64 t; cvta.to.shared.u64 t, %1; cvt.u32.u64 %0, t; }" : "=r"(a) : "l"(p));
    return a;
}
__device__ __forceinline__ void cp16(uint32_t dst, const void* src) {
    asm volatile("cp.async.cg.shared.global [%0], [%1], 16;" :: "r"(dst), "l"(src) : "memory");
}
#define CP_COMMIT()  asm volatile("cp.async.commit_group;" ::: "memory")
#define CP_WAIT(N)   asm volatile("cp.async.wait_group %0;" :: "n"(N) : "memory")

__device__ __forceinline__ void ldsm4(uint32_t r[4], uint32_t addr) {
    asm volatile("ldmatrix.sync.aligned.m8n8.x4.shared.b16 {%0,%1,%2,%3}, [%4];"
                 : "=r"(r[0]), "=r"(r[1]), "=r"(r[2]), "=r"(r[3]) : "r"(addr));
}
__device__ __forceinline__ void mma16816(float c[4], const uint32_t a[4],
                                         uint32_t b0, uint32_t b1) {
    asm volatile(
        "mma.sync.aligned.m16n8k16.row.col.f32.f16.f16.f32 "
        "{%0,%1,%2,%3}, {%4,%5,%6,%7}, {%8,%9}, {%0,%1,%2,%3};"
        : "+f"(c[0]), "+f"(c[1]), "+f"(c[2]), "+f"(c[3])
        : "r"(a[0]), "r"(a[1]), "r"(a[2]), "r"(a[3]), "r"(b0), "r"(b1));
}

// ---------------------------------------------------------------------------
// K1: prep = wsplit (+tables) ∪ xhalf, one launch.
//   blocks [0, NWB)            : W transpose block (bx, by, w)
//   blocks [NWB, NWB + XB)     : x -> fp16 chunk
// ---------------------------------------------------------------------------
#define NWB_MAX (8 * 8 * NW_MAX)

__global__ __launch_bounds__(256) void prep(
    const float* __restrict__ weight,
    const int* __restrict__ seg1,
    const int* __restrict__ seg2,
    const float* __restrict__ x,
    int nnz, int G, int nwb, int xn4) {

    __shared__ float tile[32][33];
    const int blk = blockIdx.x;
    const int tid = threadIdx.x;

    if (blk >= nwb) {
        // ---- xhalf role ----
        int i = (blk - nwb) * 256 + tid;
        if (i < xn4) {
            float4 v = __ldg(reinterpret_cast<const float4*>(x) + i);
            __half2 a = __floats2half2_rn(v.x, v.y);
            __half2 b = __floats2half2_rn(v.z, v.w);
            reinterpret_cast<uint2*>(g_xh)[i] =
                make_uint2(*(uint32_t*)&a, *(uint32_t*)&b);
        }
        return;
    }

    // ---- wsplit role ----
    const int bx = blk & 7;          // co block
    const int by = (blk >> 3) & 7;   // ci block
    const int w  = blk >> 6;
    const int tx = tid & 31;
    const int ty = tid >> 5;

    if (blk == 0) {
        for (int i = tid; i < nnz; i += 256) {
            if (i == 0) g_gs[seg1[0]] = 0;
            else if (seg1[i] != seg1[i - 1]) g_gs[seg1[i]] = i;
        }
        for (int i = tid; i < G; i += 256) {
            if (i == 0) g_mg[seg2[0]] = 0;
            else if (seg2[i] != seg2[i - 1]) g_mg[seg2[i]] = i;
        }
        if (tid == 0) { g_gs[G] = nnz; g_mg[NORD] = G; }
    }

    const float* in = weight + (size_t)w * CI * CO;
#pragma unroll
    for (int j = 0; j < 4; ++j) {
        int r = ty + 8 * j;
        tile[r][tx] = in[(size_t)(by * 32 + r) * CO + bx * 32 + tx];
    }
    __syncthreads();
#pragma unroll
    for (int j = 0; j < 4; ++j) {
        int r = ty + 8 * j;
        float v = tile[tx][r];
        size_t o = ((size_t)w * CO + (bx * 32 + r)) * CI + by * 32 + tx;
        g_wf[o] = __float2half(v);
    }
}

// ---------------------------------------------------------------------------
// K2: build inter from fp16 x. Block = 8 b values (32 threads per b, thread
// owns 8 ci). Grid (Bn/8, 8): g-range split x8. Normal stores (L2-resident).
// ---------------------------------------------------------------------------
__global__ __launch_bounds__(256) void build_inter(
    const float* __restrict__ sh,
    const float* __restrict__ CG,
    const int* __restrict__ M1,
    const int* __restrict__ M2,
    int G, int Bn) {

    __shared__ float coefs[8][NNZ_MAX];   // 16KB
    __shared__ int   m1s[NNZ_MAX];
    __shared__ int   gs_s[G_MAX + 1];

    const int b_base = blockIdx.x * 8;
    const int q      = blockIdx.y;
    const int tid    = threadIdx.x;
    const int bsub   = tid >> 5;          // 0..7
    const int c8     = (tid & 31) * 8;    // ci base (8 per thread)

    const int gq0 = (G * q) >> 3;
    const int gq1 = (G * (q + 1)) >> 3;

    for (int i = tid; i <= G; i += 256) gs_s[i] = g_gs[i];
    __syncthreads();
    const int n0 = gs_s[gq0];
    const int n1 = gs_s[gq1];

    for (int i = n0 + tid; i < n1; i += 256) m1s[i] = M1[i] * CI;
#pragma unroll
    for (int bb = 0; bb < 8; ++bb) {
        const float* shb = sh + (size_t)(b_base + bb) * NORD;
        for (int i = n0 + tid; i < n1; i += 256)
            coefs[bb][i] = CG[i] * shb[M2[i]];
    }
    __syncthreads();

    const int b = b_base + bsub;
    const __half* xb = g_xh + (size_t)b * NORD * CI + c8;
    const float* cf = coefs[bsub];

    for (int g = gq0; g < gq1; ++g) {
        float acc[8];
#pragma unroll
        for (int j = 0; j < 8; ++j) acc[j] = 0.f;
        const int e = gs_s[g + 1];
        for (int idx = gs_s[g]; idx < e; ++idx) {
            const float c = cf[idx];
            uint4 v = *reinterpret_cast<const uint4*>(xb + m1s[idx]);
            float2 f0 = __half22float2(*reinterpret_cast<__half2*>(&v.x));
            float2 f1 = __half22float2(*reinterpret_cast<__half2*>(&v.y));
            float2 f2 = __half22float2(*reinterpret_cast<__half2*>(&v.z));
            float2 f3 = __half22float2(*reinterpret_cast<__half2*>(&v.w));
            acc[0] = fmaf(c, f0.x, acc[0]);
            acc[1] = fmaf(c, f0.y, acc[1]);
            acc[2] = fmaf(c, f1.x, acc[2]);
            acc[3] = fmaf(c, f1.y, acc[3]);
            acc[4] = fmaf(c, f2.x, acc[4]);
            acc[5] = fmaf(c, f2.y, acc[5]);
            acc[6] = fmaf(c, f3.x, acc[6]);
            acc[7] = fmaf(c, f3.y, acc[7]);
        }
        __half2 p0 = __floats2half2_rn(acc[0], acc[1]);
        __half2 p1 = __floats2half2_rn(acc[2], acc[3]);
        __half2 p2 = __floats2half2_rn(acc[4], acc[5]);
        __half2 p3 = __floats2half2_rn(acc[6], acc[7]);
        uint4 v = make_uint4(*(uint32_t*)&p0, *(uint32_t*)&p1,
                             *(uint32_t*)&p2, *(uint32_t*)&p3);
        *reinterpret_cast<uint4*>(g_af + ((size_t)g * Bn + b) * CI + c8) = v;
    }
}

// ---------------------------------------------------------------------------
// K3: mma.sync GEMM (R10/R14 best geometry). Grid (Bn/64, CO/128, NORD),
// 128 threads (4 warps: 2m x 2n, warp tile 32x64). KT=64.
// Stage 24KB: A 8K | W 16K. Double buffered -> 48KB+1K, 4 CTAs/SM.
// ---------------------------------------------------------------------------
#define KT          64
#define OFF_W       8192
#define STAGE_BYTES 24576
#define SMEM_DYN    (2 * STAGE_BYTES + 1024)

__device__ __forceinline__ void load_stage(uint32_t st,
                                           const char* gA, const char* gW,
                                           int tid) {
#pragma unroll
    for (int i = 0; i < 4; ++i) {          // A: 64 rows x 8 chunks of 16B
        int idx = tid + i * 128;
        int r = idx >> 3, c = idx & 7;
        cp16(st + SWZ(r * 128 + c * 16), gA + (size_t)r * (CI * 2) + c * 16);
    }
#pragma unroll
    for (int i = 0; i < 8; ++i) {          // W: 128 rows x 8 chunks
        int idx = tid + i * 128;
        int r = idx >> 3, c = idx & 7;
        cp16(st + OFF_W + SWZ(r * 128 + c * 16), gW + (size_t)r * (CI * 2) + c * 16);
    }
}

__global__ __launch_bounds__(128, 4) void so3_mma(
    const int* __restrict__ l_ind,
    float* __restrict__ out,
    int Bn) {

    extern __shared__ char smem[];
    const uint32_t sb   = smem_u32(smem);
    const uint32_t base = (sb + 1023) & ~1023u;

    const int tid  = threadIdx.x;
    const int wid  = tid >> 5;
    const int lane = tid & 31;
    const int wm   = wid & 1;          // 2 m-warps (32 rows each)
    const int wn   = wid >> 1;         // 2 n-warps (64 cols each)

    const int b0  = blockIdx.x * 64;
    const int cob = blockIdx.y * 128;
    const int M   = c_morder[blockIdx.z];
    const int gbeg = g_mg[M];
    const int gend = g_mg[M + 1];
    const int T = (gend - gbeg) * (CI / KT);   // k-tiles (4 per group)

    float acc[2][8][4];
#pragma unroll
    for (int i = 0; i < 2; ++i)
#pragma unroll
        for (int j = 0; j < 8; ++j)
#pragma unroll
            for (int q = 0; q < 4; ++q) acc[i][j][q] = 0.f;

    auto srcA = [&](int t) -> const char* {
        int g = gbeg + (t >> 2), kc = t & 3;
        return (const char*)g_af + (((size_t)g * Bn + b0) * CI + kc * KT) * 2;
    };
    auto srcW = [&](int t) -> const char* {
        int g = gbeg + (t >> 2), kc = t & 3;
        int w = __ldg(l_ind + g);
        return (const char*)g_wf + (((size_t)w * CO + cob) * CI + kc * KT) * 2;
    };

    // prologue
    load_stage(base, srcA(0), srcW(0), tid);
    CP_COMMIT();

    // ldmatrix lane addressing
    const int arow = wm * 32 + (lane & 15);
    const int acol = (lane >> 4) * 16;
    const int wrow = wn * 64 + (lane & 7) + ((lane >> 4) << 3);
    const int wcol = ((lane >> 3) & 1) * 16;

    for (int t = 0; t < T; ++t) {
        const uint32_t st = base + (uint32_t)(t & 1) * STAGE_BYTES;

        if (t + 1 < T) {
            const uint32_t stn = base + (uint32_t)((t + 1) & 1) * STAGE_BYTES;
            load_stage(stn, srcA(t + 1), srcW(t + 1), tid);
            CP_COMMIT();
            CP_WAIT(1);
        } else {
            CP_WAIT(0);
        }
        __syncthreads();

#pragma unroll
        for (int ks = 0; ks < KT / 16; ++ks) {
            const int kb = ks * 32;                // 16 fp16 = 32B
            uint32_t af[2][4];
#pragma unroll
            for (int mi = 0; mi < 2; ++mi) {
                uint32_t ad = st + SWZ((arow + mi * 16) * 128 + kb + acol);
                ldsm4(af[mi], ad);
            }
#pragma unroll
            for (int j = 0; j < 4; ++j) {          // four n16 chunks (64 cols)
                uint32_t wf[4];
                uint32_t wd = st + OFF_W + SWZ((wrow + j * 16) * 128 + kb + wcol);
                ldsm4(wf, wd);
#pragma unroll
                for (int mi = 0; mi < 2; ++mi)
#pragma unroll
                    for (int s = 0; s < 2; ++s)
                        mma16816(acc[mi][j * 2 + s], af[mi], wf[s * 2], wf[s * 2 + 1]);
            }
        }
        __syncthreads();
    }

    // epilogue: out[b0+.., M, cob+..] written exactly once
#pragma unroll
    for (int mi = 0; mi < 2; ++mi) {
        const int m0 = b0 + wm * 32 + mi * 16 + (lane >> 2);
#pragma unroll
        for (int j = 0; j < 8; ++j) {
            const int n = cob + wn * 64 + j * 8 + (lane & 3) * 2;
            float* p0 = out + ((size_t)m0 * NORD + M) * CO + n;
            float* p1 = out + ((size_t)(m0 + 8) * NORD + M) * CO + n;
            *(float2*)p0 = make_float2(acc[mi][j][0], acc[mi][j][1]);
            *(float2*)p1 = make_float2(acc[mi][j][2], acc[mi][j][3]);
        }
    }
}

// ---------------------------------------------------------------------------
// Inputs: x, sh, weight, CG_vals, M1, M2, seg1, l_ind, seg2, num_orders_out
// ---------------------------------------------------------------------------
extern "C" void kernel_launch(void* const* d_in, const int* in_sizes, int n_in,
                              void* d_out, int out_size) {
    const float* x      = (const float*)d_in[0];
    const float* sh     = (const float*)d_in[1];
    const float* weight = (const float*)d_in[2];
    const float* CG     = (const float*)d_in[3];
    const int*   M1     = (const int*)d_in[4];
    const int*   M2     = (const int*)d_in[5];
    const int*   seg1   = (const int*)d_in[6];
    const int*   l_ind  = (const int*)d_in[7];
    const int*   seg2   = (const int*)d_in[8];
    float*       out    = (float*)d_out;

    const int nnz = in_sizes[4];
    const int G   = in_sizes[7];
    const int Bn  = in_sizes[1] / NORD;
    const int n_w = in_sizes[2] / (CI * CO);
    const int xn4 = in_sizes[0] / 4;

    static bool attr_set = false;
    if (!attr_set) {
        cudaFuncSetAttribute(so3_mma, cudaFuncAttributeMaxDynamicSharedMemorySize, SMEM_DYN);
        attr_set = true;
    }

    const int nwb = 8 * 8 * n_w;                       // wsplit blocks
    const int xb  = (xn4 + 255) / 256;                 // xhalf blocks
    prep<<<nwb + xb, 256>>>(weight, seg1, seg2, x, nnz, G, nwb, xn4);
    {
        dim3 grid(Bn / 8, 8);
        build_inter<<<grid, 256>>>(sh, CG, M1, M2, G, Bn);
    }
    {
        dim3 grid(Bn / 64, CO / 128, NORD);
        so3_mma<<<grid, 128, SMEM_DYN>>>(l_ind, out, Bn);
    }
}